// round 1
// baseline (speedup 1.0000x reference)
#include <cuda_runtime.h>
#include <math.h>

// Cox partial likelihood loss:
//   rss[i] = sum_j exp(theta_j) * [T_j >= T_i]
//   loss   = -mean( (theta_i - log(rss_i)) * ev_i )
//
// Brute-force O(N^2) compare-accumulate, 2D-tiled:
//   grid.x = i-chunks (1024 i per CTA, 4 per thread)
//   grid.y = j-chunks (16 splits of the j range)
// Partial sums written to scratch, combined deterministically.

#define N_MAX 16384
#define TPB   256
#define RPT   4                 // i-values per thread
#define IPB   (TPB * RPT)       // 1024 i per CTA
#define JS    16                // j splits

__device__ float2 g_pair[N_MAX];            // (T_j, exp(theta_j))
__device__ float  g_partial[JS * N_MAX];    // per-j-chunk partial risk sums
__device__ float  g_red[N_MAX / TPB];       // per-block loss partials (64)

__global__ void prep_kernel(const float* __restrict__ theta,
                            const float* __restrict__ T, int n) {
    int i = blockIdx.x * blockDim.x + threadIdx.x;
    if (i < n) g_pair[i] = make_float2(T[i], expf(theta[i]));
}

__global__ void risk_kernel(const float* __restrict__ T, int n) {
    const int jcnt  = n / JS;                 // 1024
    const int jbase = blockIdx.y * jcnt;

    // Whole j-chunk staged in SMEM as float4 = (T0,e0,T1,e1): 8 KB
    __shared__ float4 sp[N_MAX / JS / 2];     // 512 float4

    const float4* src = reinterpret_cast<const float4*>(g_pair + jbase);
    for (int k = threadIdx.x; k < jcnt / 2; k += TPB) sp[k] = src[k];
    __syncthreads();

    const int i0 = blockIdx.x * IPB + threadIdx.x;

    float Ti[RPT], acc[RPT];
#pragma unroll
    for (int r = 0; r < RPT; r++) {
        Ti[r]  = T[i0 + r * TPB];
        acc[r] = 0.0f;
    }

#pragma unroll 4
    for (int k = 0; k < jcnt / 2; k++) {
        float4 p = sp[k];                     // broadcast LDS.128 (uniform addr)
#pragma unroll
        for (int r = 0; r < RPT; r++) {
            if (p.x >= Ti[r]) acc[r] += p.y;  // FSETP + @P FADD
            if (p.z >= Ti[r]) acc[r] += p.w;
        }
    }

#pragma unroll
    for (int r = 0; r < RPT; r++)
        g_partial[blockIdx.y * N_MAX + i0 + r * TPB] = acc[r];
}

__global__ void combine_kernel(const float* __restrict__ theta,
                               const float* __restrict__ ev, int n) {
    __shared__ float red[TPB];
    const int i = blockIdx.x * TPB + threadIdx.x;

    float rss = 0.0f;
#pragma unroll
    for (int jc = 0; jc < JS; jc++) rss += g_partial[jc * N_MAX + i];

    float term = (theta[i] - logf(rss)) * ev[i];
    red[threadIdx.x] = term;
    __syncthreads();
#pragma unroll
    for (int s = TPB / 2; s > 0; s >>= 1) {
        if (threadIdx.x < s) red[threadIdx.x] += red[threadIdx.x + s];
        __syncthreads();
    }
    if (threadIdx.x == 0) g_red[blockIdx.x] = red[0];
}

__global__ void final_kernel(float* __restrict__ out, int n, int nb) {
    __shared__ float red[64];
    float v = (threadIdx.x < nb) ? g_red[threadIdx.x] : 0.0f;
    red[threadIdx.x] = v;
    __syncthreads();
#pragma unroll
    for (int s = 32; s > 0; s >>= 1) {
        if (threadIdx.x < s) red[threadIdx.x] += red[threadIdx.x + s];
        __syncthreads();
    }
    if (threadIdx.x == 0) out[0] = -red[0] / (float)n;
}

extern "C" void kernel_launch(void* const* d_in, const int* in_sizes, int n_in,
                              void* d_out, int out_size) {
    const float* theta = (const float*)d_in[0];   // risk_scores
    const float* T     = (const float*)d_in[1];   // survival_times
    const float* ev    = (const float*)d_in[2];   // events
    float*       out   = (float*)d_out;
    const int n = in_sizes[0];                    // 16384

    prep_kernel<<<(n + 255) / 256, 256>>>(theta, T, n);

    dim3 grid(n / IPB, JS);                       // (16, 16)
    risk_kernel<<<grid, TPB>>>(T, n);

    combine_kernel<<<n / TPB, TPB>>>(theta, ev, n);
    final_kernel<<<1, 64>>>(out, n, n / TPB);
}

// round 2
// speedup vs baseline: 1.0603x; 1.0603x over previous
#include <cuda_runtime.h>
#include <math.h>

// Cox partial likelihood via chunk-sorted suffix sums:
//   u_j  = order-preserving uint32 key of T_j
//   Partition j into CH chunks of 512; per chunk: bitonic sort by u,
//   suffix-sum e_j = exp(theta_j).
//   rss[i] = sum_c suffix_c[ lower_bound_c(u_i) ]
//   loss   = -mean( (theta_i - log(rss_i)) * ev_i )

#define NSORT 512
#define MAXC  32              // 16384 / 512

__device__ unsigned g_u[MAXC * NSORT];         // sorted keys per chunk
__device__ float    g_sfx[MAXC * (NSORT + 1)]; // suffix sums (+ trailing 0)

__device__ __forceinline__ unsigned key_of(float t) {
    unsigned b = __float_as_uint(t);
    return b ^ ((unsigned)((int)b >> 31) | 0x80000000u);
}

__global__ void __launch_bounds__(NSORT)
sort_kernel(const float* __restrict__ theta, const float* __restrict__ T,
            int n, float* __restrict__ out) {
    const int c = blockIdx.x;
    const int t = threadIdx.x;
    const int j = c * NSORT + t;

    unsigned u = 0u;     // pad: smaller than any real key (real keys never 0)
    float    e = 0.0f;
    if (j < n) {
        u = key_of(T[j]);
        e = expf(theta[j]);
    }

    __shared__ unsigned su[NSORT];
    __shared__ float    se[NSORT];
    su[t] = u;
    se[t] = e;
    __syncthreads();

    // Bitonic sort ascending by key (fixed network -> deterministic)
    for (int k = 2; k <= NSORT; k <<= 1) {
        for (int s = k >> 1; s > 0; s >>= 1) {
            int ixj = t ^ s;
            if (ixj > t) {
                unsigned a = su[t], b = su[ixj];
                bool up = ((t & k) == 0);
                if ((a > b) == up) {
                    su[t] = b;  su[ixj] = a;
                    float ea = se[t];
                    se[t] = se[ixj]; se[ixj] = ea;
                }
            }
            __syncthreads();
        }
    }

    // Inclusive suffix sum of se (Hillis-Steele, reversed)
    for (int d = 1; d < NSORT; d <<= 1) {
        float tmp = (t + d < NSORT) ? se[t + d] : 0.0f;
        __syncthreads();
        se[t] += tmp;
        __syncthreads();
    }

    g_u[c * NSORT + t]          = su[t];
    g_sfx[c * (NSORT + 1) + t]  = se[t];
    if (t == 0) {
        g_sfx[c * (NSORT + 1) + NSORT] = 0.0f;
        if (c == 0) out[0] = 0.0f;     // init accumulator (runs before loss_kernel)
    }
}

__global__ void __launch_bounds__(128)
loss_kernel(const float* __restrict__ theta, const float* __restrict__ T,
            const float* __restrict__ ev, int n, int chunks,
            float* __restrict__ out) {
    const int i = blockIdx.x * 128 + threadIdx.x;

    float term = 0.0f;
    if (i < n) {
        const unsigned u = key_of(T[i]);
        float rss = 0.0f;
#pragma unroll 4
        for (int c = 0; c < chunks; c++) {
            const unsigned* __restrict__ A = g_u + c * NSORT;
            int lo = 0;
#pragma unroll
            for (int s = NSORT / 2; s > 0; s >>= 1)
                if (__ldg(A + lo + s - 1) < u) lo += s;
            rss += __ldg(g_sfx + c * (NSORT + 1) + lo);
        }
        term = (theta[i] - logf(rss)) * ev[i];
    }

    // Block reduce: warp shuffles + SMEM across 4 warps
    for (int off = 16; off > 0; off >>= 1)
        term += __shfl_down_sync(0xFFFFFFFFu, term, off);

    __shared__ float wsum[4];
    const int lane = threadIdx.x & 31, warp = threadIdx.x >> 5;
    if (lane == 0) wsum[warp] = term;
    __syncthreads();
    if (threadIdx.x == 0) {
        float s = wsum[0] + wsum[1] + wsum[2] + wsum[3];
        atomicAdd(out, -s / (float)n);
    }
}

extern "C" void kernel_launch(void* const* d_in, const int* in_sizes, int n_in,
                              void* d_out, int out_size) {
    const float* theta = (const float*)d_in[0];   // risk_scores
    const float* T     = (const float*)d_in[1];   // survival_times
    const float* ev    = (const float*)d_in[2];   // events
    float*       out   = (float*)d_out;
    const int n = in_sizes[0];                    // 16384

    const int chunks = (n + NSORT - 1) / NSORT;   // 32

    sort_kernel<<<chunks, NSORT>>>(theta, T, n, out);
    loss_kernel<<<(n + 127) / 128, 128>>>(theta, T, ev, n, chunks, out);
}